// round 1
// baseline (speedup 1.0000x reference)
#include <cuda_runtime.h>
#include <cstdint>

// Problem constants
#define NN 50000
#define NE 800000
#define DH 64

// Scratch (device globals: no allocation allowed)
__device__ float g_h[NN * DH];     // node features (current block input)
__device__ float g_A[NN * DH];     // h @ w0[:64]   (src half)
__device__ float g_B[NN * DH];     // h @ w0[64:]   (dst half)
__device__ float g_agg[NN * DH];   // scatter-accumulated u
__device__ float g_deg[NN];        // in-degree (float)
__device__ int   g_is64;           // edge_index dtype flag (1 = int64, 0 = int32)

// ---------------------------------------------------------------------------
// Detect whether edge_index is int64 or int32 (JAX may silently emit int32).
// For int64 nonnegative indices every odd 32-bit word (high half) is zero;
// for int32 the odd words are edge values and are ~never all zero.
// ---------------------------------------------------------------------------
__global__ void detect_kernel(const int* __restrict__ ei32) {
    __shared__ int any;
    if (threadIdx.x == 0) any = 0;
    __syncthreads();
    for (int i = threadIdx.x; i < 4096; i += 256) {
        if (ei32[2 * i + 1] != 0) any = 1;  // benign race, all write 1
    }
    __syncthreads();
    if (threadIdx.x == 0) g_is64 = (any == 0) ? 1 : 0;
}

__device__ __forceinline__ void load_edge(const void* ei, int e, int& src, int& dst) {
    if (g_is64) {
        const long long* p = (const long long*)ei;
        src = (int)p[e];
        dst = (int)p[NE + e];
    } else {
        const int* p = (const int*)ei;
        src = p[e];
        dst = p[NE + e];
    }
}

// ---------------------------------------------------------------------------
// h = x @ lin_in_w + lin_in_b   ([50000,16] @ [16,64])
// Block: 256 threads = 4 nodes x 64 outputs. Grid 12500 (exact).
// ---------------------------------------------------------------------------
__global__ void lin_in_kernel(const float* __restrict__ x,
                              const float* __restrict__ w,
                              const float* __restrict__ b) {
    __shared__ float ws[16 * 64];
    __shared__ float bs[64];
    __shared__ float xs[4][16];
    int tid = threadIdx.x;
    for (int i = tid; i < 16 * 64; i += 256) ws[i] = w[i];
    if (tid < 64) bs[tid] = b[tid];
    if (tid < 64) {
        int nl = tid >> 4, c = tid & 15;
        int n = blockIdx.x * 4 + nl;
        xs[nl][c] = x[n * 16 + c];
    }
    __syncthreads();
    int j = tid & 63, nl = tid >> 6;
    int n = blockIdx.x * 4 + nl;
    float acc = bs[j];
#pragma unroll
    for (int c = 0; c < 16; c++) acc = fmaf(xs[nl][c], ws[c * 64 + j], acc);
    g_h[n * 64 + j] = acc;
}

// ---------------------------------------------------------------------------
// Degree computation
// ---------------------------------------------------------------------------
__global__ void zero_deg_kernel() {
    int i = blockIdx.x * 256 + threadIdx.x;
    if (i < NN) g_deg[i] = 0.0f;
}

__global__ void count_deg_kernel(const void* __restrict__ ei) {
    int e = blockIdx.x * 256 + threadIdx.x;  // grid exact: 3125*256 = 800000
    int src, dst;
    load_edge(ei, e, src, dst);
    atomicAdd(&g_deg[dst], 1.0f);
}

__global__ void zero_agg_kernel() {
    int i = blockIdx.x * 256 + threadIdx.x;  // grid exact: 12500*256 = 3.2M
    g_agg[i] = 0.0f;
}

// ---------------------------------------------------------------------------
// A = h @ w0[0:64,:],  B = h @ w0[64:128,:]
// Block: 256 threads = 4 groups x 64 outputs; each thread handles 4 nodes.
// 16 nodes/block, grid 3125 (exact).
// ---------------------------------------------------------------------------
__global__ __launch_bounds__(256) void nodeAB_kernel(const float* __restrict__ w0k) {
    __shared__ float w0s[128 * 64];  // 32 KB
    __shared__ float hs[16][64];     // 4 KB
    int tid = threadIdx.x;
    for (int i = tid; i < 128 * 64; i += 256) w0s[i] = w0k[i];
    int n0 = blockIdx.x * 16;
    for (int i = tid; i < 16 * 64; i += 256)
        hs[i >> 6][i & 63] = g_h[(n0 + (i >> 6)) * 64 + (i & 63)];
    __syncthreads();
    int j = tid & 63, grp = tid >> 6;
    float a[4] = {0, 0, 0, 0}, bb[4] = {0, 0, 0, 0};
#pragma unroll 8
    for (int c = 0; c < 64; c++) {
        float wa = w0s[c * 64 + j];
        float wb = w0s[(64 + c) * 64 + j];
#pragma unroll
        for (int i = 0; i < 4; i++) {
            float hv = hs[grp * 4 + i][c];
            a[i]  = fmaf(hv, wa, a[i]);
            bb[i] = fmaf(hv, wb, bb[i]);
        }
    }
#pragma unroll
    for (int i = 0; i < 4; i++) {
        int n = n0 + grp * 4 + i;
        g_A[n * 64 + j] = a[i];
        g_B[n * 64 + j] = bb[i];
    }
}

// ---------------------------------------------------------------------------
// Edge kernel: the hot loop.
//   t = relu(A[src] + B[dst] + b0)        (t[64] in registers)
//   u = relu(t @ w1 + b1)                 (w1 in SMEM, broadcast LDS.128)
//   agg[dst] += u                         (red.global.add.v4.f32, 16/edge)
// One thread per edge, 256 threads/block, grid 3125 (exact).
// ---------------------------------------------------------------------------
__global__ __launch_bounds__(256) void edge_kernel(const void* __restrict__ ei,
                                                   const float* __restrict__ w1,
                                                   const float* __restrict__ b0,
                                                   const float* __restrict__ b1) {
    __shared__ __align__(16) float w1s[64 * 64];  // 16 KB
    __shared__ __align__(16) float b0s[64];
    __shared__ __align__(16) float b1s[64];
    int tid = threadIdx.x;
    for (int i = tid; i < 64 * 64; i += 256) w1s[i] = w1[i];
    if (tid < 64) { b0s[tid] = b0[tid]; b1s[tid] = b1[tid]; }
    __syncthreads();

    int e = blockIdx.x * 256 + tid;
    int src, dst;
    load_edge(ei, e, src, dst);

    const float4* Ar = (const float4*)(g_A + src * 64);
    const float4* Br = (const float4*)(g_B + dst * 64);

    float t[64];
#pragma unroll
    for (int q = 0; q < 16; q++) {
        float4 a = __ldg(&Ar[q]);
        float4 b = __ldg(&Br[q]);
        float4 c = ((const float4*)b0s)[q];
        t[4 * q + 0] = fmaxf(a.x + b.x + c.x, 0.0f);
        t[4 * q + 1] = fmaxf(a.y + b.y + c.y, 0.0f);
        t[4 * q + 2] = fmaxf(a.z + b.z + c.z, 0.0f);
        t[4 * q + 3] = fmaxf(a.w + b.w + c.w, 0.0f);
    }

    float* outp = g_agg + dst * 64;
#pragma unroll 2
    for (int jg = 0; jg < 16; jg++) {
        float4 u = ((const float4*)b1s)[jg];
#pragma unroll
        for (int k = 0; k < 64; k++) {
            float4 w = *(const float4*)(w1s + k * 64 + jg * 4);  // broadcast
            u.x = fmaf(t[k], w.x, u.x);
            u.y = fmaf(t[k], w.y, u.y);
            u.z = fmaf(t[k], w.z, u.z);
            u.w = fmaf(t[k], w.w, u.w);
        }
        u.x = fmaxf(u.x, 0.0f);
        u.y = fmaxf(u.y, 0.0f);
        u.z = fmaxf(u.z, 0.0f);
        u.w = fmaxf(u.w, 0.0f);
        float* d4 = outp + jg * 4;
        asm volatile("red.global.add.v4.f32 [%0], {%1, %2, %3, %4};"
                     :: "l"(d4), "f"(u.x), "f"(u.y), "f"(u.z), "f"(u.w)
                     : "memory");
    }
}

// ---------------------------------------------------------------------------
// h = agg @ w2 + deg * b2   ([50000,64] @ [64,64])
// Same tiling as nodeAB. Grid 3125 (exact).
// ---------------------------------------------------------------------------
__global__ __launch_bounds__(256) void nodeOut_kernel(const float* __restrict__ w2k,
                                                      const float* __restrict__ b2k) {
    __shared__ float ws[64 * 64];  // 16 KB
    __shared__ float hs[16][64];
    __shared__ float bs[64];
    int tid = threadIdx.x;
    for (int i = tid; i < 64 * 64; i += 256) ws[i] = w2k[i];
    if (tid < 64) bs[tid] = b2k[tid];
    int n0 = blockIdx.x * 16;
    for (int i = tid; i < 16 * 64; i += 256)
        hs[i >> 6][i & 63] = g_agg[(n0 + (i >> 6)) * 64 + (i & 63)];
    __syncthreads();
    int j = tid & 63, grp = tid >> 6;
    float acc[4];
#pragma unroll
    for (int i = 0; i < 4; i++) acc[i] = g_deg[n0 + grp * 4 + i] * bs[j];
#pragma unroll 8
    for (int c = 0; c < 64; c++) {
        float wv = ws[c * 64 + j];
#pragma unroll
        for (int i = 0; i < 4; i++)
            acc[i] = fmaf(hs[grp * 4 + i][c], wv, acc[i]);
    }
#pragma unroll
    for (int i = 0; i < 4; i++)
        g_h[(n0 + grp * 4 + i) * 64 + j] = acc[i];
}

// ---------------------------------------------------------------------------
// out = h @ lin_out_w + lin_out_b   ([50000,64] @ [64,16])
// Block: 256 threads = 16 nodes x 16 outputs. Grid 3125 (exact).
// ---------------------------------------------------------------------------
__global__ void lin_out_kernel(const float* __restrict__ w,
                               const float* __restrict__ b,
                               float* __restrict__ out) {
    __shared__ float ws[64 * 16];
    __shared__ float bs[16];
    __shared__ float hs[16][64];
    int tid = threadIdx.x;
    for (int i = tid; i < 64 * 16; i += 256) ws[i] = w[i];
    if (tid < 16) bs[tid] = b[tid];
    int n0 = blockIdx.x * 16;
    for (int i = tid; i < 16 * 64; i += 256)
        hs[i >> 6][i & 63] = g_h[(n0 + (i >> 6)) * 64 + (i & 63)];
    __syncthreads();
    int j = tid & 15, nl = tid >> 4;
    float acc = bs[j];
#pragma unroll 16
    for (int c = 0; c < 64; c++)
        acc = fmaf(hs[nl][c], ws[c * 16 + j], acc);
    out[(n0 + nl) * 16 + j] = acc;
}

// ---------------------------------------------------------------------------
// Launch
// ---------------------------------------------------------------------------
extern "C" void kernel_launch(void* const* d_in, const int* in_sizes, int n_in,
                              void* d_out, int out_size) {
    const float* x        = (const float*)d_in[0];
    // d_in[1] = lframes (unused by the reference)
    const void*  ei       = d_in[2];
    const float* lin_in_w = (const float*)d_in[3];
    const float* lin_in_b = (const float*)d_in[4];
    const float* w0       = (const float*)d_in[5];
    const float* b0       = (const float*)d_in[6];
    const float* w1       = (const float*)d_in[7];
    const float* b1       = (const float*)d_in[8];
    const float* w2       = (const float*)d_in[9];
    const float* b2       = (const float*)d_in[10];
    const float* low      = (const float*)d_in[11];
    const float* lob      = (const float*)d_in[12];
    float* out = (float*)d_out;

    detect_kernel<<<1, 256>>>((const int*)ei);
    lin_in_kernel<<<NN / 4, 256>>>(x, lin_in_w, lin_in_b);
    zero_deg_kernel<<<(NN + 255) / 256, 256>>>();
    count_deg_kernel<<<NE / 256, 256>>>(ei);

    for (int k = 0; k < 4; k++) {
        nodeAB_kernel<<<NN / 16, 256>>>(w0 + k * 128 * 64);
        zero_agg_kernel<<<NN * 64 / 256, 256>>>();
        edge_kernel<<<NE / 256, 256>>>(ei, w1 + k * 64 * 64, b0 + k * 64, b1 + k * 64);
        nodeOut_kernel<<<NN / 16, 256>>>(w2 + k * 64 * 64, b2 + k * 64);
    }

    lin_out_kernel<<<NN / 16, 256>>>(low, lob, out);
}